// round 12
// baseline (speedup 1.0000x reference)
#include <cuda_runtime.h>
#include <cuda_bf16.h>
#include <cstdint>

#define NB  4
#define NC  512
#define NN  4096
#define NCQ 64

// ---------------- device scratch ----------------
__device__ float g_Wr[640 * NC];                     // rounded unified [wq;wk;wv]
__device__ float g_Q[NB * NN * NCQ];                 // [b][n][k] tf32-rounded
__device__ float g_K[NB * NN * NCQ];                 // [b][m][k] tf32-rounded
__device__ __nv_bfloat16 g_Vh[(size_t)NB * NN * NC]; // [b][m][c] bf16

__device__ __forceinline__ float f2tff(float v) {
    uint32_t t;
    asm("cvt.rna.tf32.f32 %0, %1;" : "=r"(t) : "f"(v));
    return __uint_as_float(t);
}
__device__ __forceinline__ uint32_t f2tffu(float v) {
    uint32_t t;
    asm("cvt.rna.tf32.f32 %0, %1;" : "=r"(t) : "f"(v));
    return t;
}

__device__ __forceinline__ void mma8(float c[4],
                                     uint32_t a0, uint32_t a1, uint32_t a2, uint32_t a3,
                                     uint32_t b0, uint32_t b1) {
    asm volatile(
        "mma.sync.aligned.m16n8k8.row.col.f32.tf32.tf32.f32 "
        "{%0,%1,%2,%3},{%4,%5,%6,%7},{%8,%9},{%0,%1,%2,%3};"
        : "+f"(c[0]), "+f"(c[1]), "+f"(c[2]), "+f"(c[3])
        : "r"(a0), "r"(a1), "r"(a2), "r"(a3), "r"(b0), "r"(b1));
}

__device__ __forceinline__ void mma16(float c[4], const uint32_t a[4],
                                      uint32_t b0, uint32_t b1) {
    asm volatile(
        "mma.sync.aligned.m16n8k16.row.col.f32.bf16.bf16.f32 "
        "{%0,%1,%2,%3},{%4,%5,%6,%7},{%8,%9},{%0,%1,%2,%3};"
        : "+f"(c[0]), "+f"(c[1]), "+f"(c[2]), "+f"(c[3])
        : "r"(a[0]), "r"(a[1]), "r"(a[2]), "r"(a[3]), "r"(b0), "r"(b1));
}

__device__ __forceinline__ void ldsm4(uint32_t r[4], uint32_t addr) {
    asm volatile("ldmatrix.sync.aligned.m8n8.x4.shared.b16 {%0,%1,%2,%3},[%4];"
                 : "=r"(r[0]), "=r"(r[1]), "=r"(r[2]), "=r"(r[3]) : "r"(addr));
}
__device__ __forceinline__ void ldsm4t(uint32_t r[4], uint32_t addr) {
    asm volatile("ldmatrix.sync.aligned.m8n8.x4.trans.shared.b16 {%0,%1,%2,%3},[%4];"
                 : "=r"(r[0]), "=r"(r[1]), "=r"(r[2]), "=r"(r[3]) : "r"(addr));
}
__device__ __forceinline__ void cpa16(uint32_t s, const void* g) {
    asm volatile("cp.async.cg.shared.global [%0],[%1],16;" :: "r"(s), "l"(g));
}

// =========================================================================
// Kernel 0: pre-round W (once) into unified g_Wr[o][c], o in [0,640).
// =========================================================================
__global__ __launch_bounds__(256) void pam_roundw(
    const float* __restrict__ wq, const float* __restrict__ wk,
    const float* __restrict__ wv)
{
    int i = blockIdx.x * 256 + threadIdx.x;      // float4 index, 81920 total
    int p = i * 4;
    int o = p >> 9, c = p & 511;
    const float* src = (o < 64) ? (wq + (size_t)o * NC + c)
                     : (o < 128) ? (wk + (size_t)(o - 64) * NC + c)
                                 : (wv + (size_t)(o - 128) * NC + c);
    float4 v = *reinterpret_cast<const float4*>(src);
    v.x = f2tff(v.x); v.y = f2tff(v.y); v.z = f2tff(v.z); v.w = f2tff(v.w);
    *reinterpret_cast<float4*>(g_Wr + p) = v;
}

// =========================================================================
// Kernel 1: fused QKV projection (unchanged from round 11 passing version).
// =========================================================================
#define PJ_WS    33792
#define SMEM_PJ  70656

__global__ __launch_bounds__(256) void pam_proj(
    const float* __restrict__ x,
    const float* __restrict__ bq, const float* __restrict__ bk,
    const float* __restrict__ bv)
{
    extern __shared__ char sm[];
    uint32_t sb = (uint32_t)__cvta_generic_to_shared(sm);
    const uint32_t AsA = sb, WsA = sb + PJ_WS;

    const int b  = blockIdx.z;
    const int n0 = blockIdx.x * 128;
    const int oc = blockIdx.y * 128;
    const int t    = threadIdx.x;
    const int lane = t & 31;
    const int wid  = t >> 5;
    const int mg = wid & 3, og = wid >> 2;
    const int m0 = mg * 32, o0 = og * 64;
    const int r0 = lane >> 2, c2 = lane & 3;

    const int wr  = ((lane >> 4) & 1) * 8 + (lane & 7);
    const int wk2 = ((lane >> 3) & 1) * 4;

    {
#pragma unroll
        for (int r = 0; r < 4; r++) {
            int idx = t + 256 * r;
            int kk = idx >> 5, j4 = idx & 31;
            cpa16(AsA + kk * 528 + j4 * 16,
                  x + ((size_t)(b * NC + kk)) * NN + n0 + j4 * 4);
        }
#pragma unroll
        for (int r = 0; r < 4; r++) {
            int idx = t + 256 * r;
            int row = idx >> 3, f4 = idx & 7;
            cpa16(WsA + row * 144 + f4 * 16,
                  g_Wr + (size_t)(oc + row) * NC + f4 * 4);
        }
        asm volatile("cp.async.commit_group;" ::: "memory");
    }

    float acc[2][8][4];
#pragma unroll
    for (int mf = 0; mf < 2; mf++)
#pragma unroll
        for (int nf = 0; nf < 8; nf++)
#pragma unroll
            for (int e = 0; e < 4; e++) acc[mf][nf][e] = 0.f;

    for (int it = 0; it < 16; it++) {
        const int buf = it & 1;
        if (it < 15) {
            const int nb = (it + 1) & 1, kc = (it + 1) * 32;
#pragma unroll
            for (int r = 0; r < 4; r++) {
                int idx = t + 256 * r;
                int kk = idx >> 5, j4 = idx & 31;
                cpa16(AsA + nb * 16896 + kk * 528 + j4 * 16,
                      x + ((size_t)(b * NC + kc + kk)) * NN + n0 + j4 * 4);
            }
#pragma unroll
            for (int r = 0; r < 4; r++) {
                int idx = t + 256 * r;
                int row = idx >> 3, f4 = idx & 7;
                cpa16(WsA + nb * 18432 + row * 144 + f4 * 16,
                      g_Wr + (size_t)(oc + row) * NC + kc + f4 * 4);
            }
            asm volatile("cp.async.commit_group;" ::: "memory");
            asm volatile("cp.async.wait_group 1;" ::: "memory");
        } else {
            asm volatile("cp.async.wait_group 0;" ::: "memory");
        }
        __syncthreads();

        const float* AsB = (const float*)(sm + buf * 16896);
        const uint32_t WsB = WsA + buf * 18432;

#pragma unroll
        for (int kq = 0; kq < 32; kq += 8) {
            uint32_t a[2][4];
#pragma unroll
            for (int mf = 0; mf < 2; mf++) {
                const float* Ab = AsB + (kq + c2) * 132 + m0 + mf * 16 + r0;
                a[mf][0] = f2tffu(Ab[0]);
                a[mf][1] = f2tffu(Ab[8]);
                a[mf][2] = f2tffu(Ab[4 * 132]);
                a[mf][3] = f2tffu(Ab[4 * 132 + 8]);
            }
#pragma unroll
            for (int i = 0; i < 4; i++) {
                uint32_t wf[4];
                ldsm4(wf, WsB + (uint32_t)(o0 + i * 16 + wr) * 144 + (kq + wk2) * 4);
                mma8(acc[0][2 * i],     a[0][0], a[0][1], a[0][2], a[0][3], wf[0], wf[1]);
                mma8(acc[0][2 * i + 1], a[0][0], a[0][1], a[0][2], a[0][3], wf[2], wf[3]);
                mma8(acc[1][2 * i],     a[1][0], a[1][1], a[1][2], a[1][3], wf[0], wf[1]);
                mma8(acc[1][2 * i + 1], a[1][0], a[1][1], a[1][2], a[1][3], wf[2], wf[3]);
            }
        }
        __syncthreads();
    }

    const int c0 = 2 * (lane & 3);
#pragma unroll
    for (int mf = 0; mf < 2; mf++) {
#pragma unroll
        for (int nf = 0; nf < 8; nf++) {
#pragma unroll
            for (int e = 0; e < 4; e++) {
                int row = m0 + mf * 16 + r0 + ((e >= 2) ? 8 : 0);
                int col = o0 + (nf >> 1) * 16 + (nf & 1) * 8 + c0 + (e & 1);
                int o = oc + col;
                int n = n0 + row;
                if (o < 64) {
                    g_Q[((size_t)b * NN + n) * NCQ + o] = f2tff(acc[mf][nf][e] + bq[o]);
                } else if (o < 128) {
                    g_K[((size_t)b * NN + n) * NCQ + (o - 64)] = f2tff(acc[mf][nf][e] + bk[o - 64]);
                } else {
                    g_Vh[((size_t)b * NN + n) * NC + (o - 128)] =
                        __float2bfloat16(acc[mf][nf][e] + bv[o - 128]);
                }
            }
        }
    }
}

// =========================================================================
// Kernel 2: FUSED attention. 64-q tile x all 512 channels per CTA.
// Per key tile: S = QK^T (tf32, once) -> P = exp(S-20) in smem ->
// O += P@V (bf16, oacc 64 regs). 1 CTA sync + 1 named barrier per tile.
// Grid 32 x 1 x 4 = 128 CTAs (one wave); each CTA persists over 2 q-tiles.
// Warp (qs = wid>>2, mg/cg = wid&3): S: 16q x 16m | PV: 16q x 128c.
// Smem: Qs f32[64][68] | Ks f32[2][64][68] | Ps bf16[64][72] |
//       Vs bf16[2][64][520] | Lpart f32[4][64] | Linv f32[64]
//       (Ostage f32[256][68] overlays Vs in epilogue)
// =========================================================================
#define AT_KS    17408
#define AT_PS    52224
#define AT_VS    61440
#define AT_LP    194560
#define AT_LI    195584
#define SMEM_AT  195840

__global__ __launch_bounds__(512, 1) void pam_attn(
    const float* __restrict__ x,
    const float* __restrict__ gamma,
    float* __restrict__ out)
{
    extern __shared__ char sm[];
    float* Lpart  = (float*)(sm + AT_LP);
    float* Linv   = (float*)(sm + AT_LI);
    float* Ostage = (float*)(sm + AT_VS);
    uint32_t sb = (uint32_t)__cvta_generic_to_shared(sm);
    const uint32_t QsA = sb, KsA = sb + AT_KS, PsA = sb + AT_PS, VsA = sb + AT_VS;

    const int b = blockIdx.z;
    const int t = threadIdx.x, lane = t & 31, wid = t >> 5;
    const int qs = wid >> 2, mg = wid & 3;       // mg doubles as cg in PV phase
    const int r0 = lane >> 2, c2 = lane & 3;

    // ldmatrix lane selectors (proven mappings)
    const int qrow = (lane & 7) + (((lane >> 3) & 1) << 3);
    const int qkof = ((lane >> 4) & 1) * 4;
    const int krow = (lane & 7) + (((lane >> 4) & 1) << 3);
    const int kkof = ((lane >> 3) & 1) * 4;
    const int ar = (lane & 7) + ((lane >> 3) & 1) * 8;
    const int ly = (lane >> 4) * 8;
    const int lx = lane & 15;
    const float gv2 = gamma[0];

    const float* gk0 = g_K + ((size_t)b * NN) * NCQ;
    const __nv_bfloat16* gv0 = g_Vh + ((size_t)b * NN) * NC;

    for (int qt = 0; qt < 2; qt++) {
        const int n0 = blockIdx.x * 128 + qt * 64;

        // ---- prologue: Q + K0 + V0, one commit group ----
        {
            const float* gq = g_Q + ((size_t)b * NN + n0) * NCQ;
#pragma unroll
            for (int r2 = 0; r2 < 2; r2++) {
                int cid = t + 512 * r2; int row = cid >> 4, c16 = cid & 15;
                cpa16(QsA + row * 272 + c16 * 16, gq + row * 64 + c16 * 4);
            }
#pragma unroll
            for (int r2 = 0; r2 < 2; r2++) {
                int cid = t + 512 * r2; int row = cid >> 4, c16 = cid & 15;
                cpa16(KsA + row * 272 + c16 * 16, gk0 + row * 64 + c16 * 4);
            }
#pragma unroll
            for (int r2 = 0; r2 < 8; r2++) {
                int cid = t + 512 * r2; int row = cid >> 6, c16 = cid & 63;
                cpa16(VsA + row * 1040 + c16 * 16, gv0 + (size_t)row * NC + c16 * 8);
            }
            asm volatile("cp.async.commit_group;" ::: "memory");
        }

        float oacc[16][4];
#pragma unroll
        for (int nf = 0; nf < 16; nf++)
#pragma unroll
            for (int e = 0; e < 4; e++) oacc[nf][e] = 0.f;
        float Lacc[2] = {0.f, 0.f};

        for (int mt = 0; mt < 64; mt++) {
            const int buf = mt & 1;
            asm volatile("cp.async.wait_group 0;" ::: "memory");
            __syncthreads();   // K/V/Q(mt) visible; everyone done with slot (mt+1)&1

            // ---- S = Q K^T (tf32), warp: 16q x 16m ----
            const uint32_t KbA = KsA + buf * 17408;
            float sacc[2][4];
#pragma unroll
            for (int nf = 0; nf < 2; nf++)
#pragma unroll
                for (int e = 0; e < 4; e++) sacc[nf][e] = 0.f;
#pragma unroll
            for (int j = 0; j < 8; j++) {
                uint32_t kf[4];
                ldsm4(kf, KbA + (uint32_t)(mg * 16 + krow) * 272 + (j * 8 + kkof) * 4);
                uint32_t qf[4];
                ldsm4(qf, QsA + (uint32_t)(qs * 16 + qrow) * 272 + (j * 8 + qkof) * 4);
                mma8(sacc[0], qf[0], qf[1], qf[2], qf[3], kf[0], kf[1]);
                mma8(sacc[1], qf[0], qf[1], qf[2], qf[3], kf[2], kf[3]);
            }

            // ---- P = exp(S - 20) -> smem bf16; accumulate L ----
#pragma unroll
            for (int nf = 0; nf < 2; nf++)
#pragma unroll
                for (int h = 0; h < 2; h++) {
                    float e0 = __expf(sacc[nf][2 * h]     - 20.f);
                    float e1 = __expf(sacc[nf][2 * h + 1] - 20.f);
                    Lacc[h] += e0 + e1;
                    uint32_t pk;
                    asm("cvt.rn.bf16x2.f32 %0, %1, %2;" : "=r"(pk) : "f"(e1), "f"(e0));
                    int q = qs * 16 + h * 8 + r0;
                    int m = mg * 16 + nf * 8 + 2 * c2;
                    *(uint32_t*)(sm + AT_PS + q * 144 + m * 2) = pk;
                }
            // P(strip qs) produced by warps (qs, mg=0..3) and consumed by the
            // same 4 warps -> named barrier over those 128 threads only.
            asm volatile("bar.sync %0, %1;" :: "r"(qs + 1), "r"(128) : "memory");

            // ---- prefetch K/V (mt+1) into the free slot (issued mid-tile) ----
            if (mt < 63) {
                const int nb = (mt + 1) & 1, m1 = (mt + 1) * 64;
                const float* gk = gk0 + (size_t)m1 * NCQ;
#pragma unroll
                for (int r2 = 0; r2 < 2; r2++) {
                    int cid = t + 512 * r2; int row = cid >> 4, c16 = cid & 15;
                    cpa16(KsA + nb * 17408 + row * 272 + c16 * 16, gk + row * 64 + c16 * 4);
                }
                const __nv_bfloat16* gvv = gv0 + (size_t)m1 * NC;
#pragma unroll
                for (int r2 = 0; r2 < 8; r2++) {
                    int cid = t + 512 * r2; int row = cid >> 6, c16 = cid & 63;
                    cpa16(VsA + nb * 66560 + row * 1040 + c16 * 16,
                          gvv + (size_t)row * NC + c16 * 8);
                }
                asm volatile("cp.async.commit_group;" ::: "memory");
            }

            // ---- O += P @ V (bf16), warp: 16q x 128c ----
            const uint32_t Vb = VsA + buf * 66560;
#pragma unroll
            for (int ks = 0; ks < 4; ks++) {
                const int k0 = ks * 16;
                uint32_t a[4];
                ldsm4(a, PsA + (uint32_t)(qs * 16 + ar) * 144 + (k0 + ly) * 2);
#pragma unroll
                for (int cb = 0; cb < 8; cb++) {
                    uint32_t bb[4];
                    ldsm4t(bb, Vb + (uint32_t)(k0 + lx) * 1040 + (mg * 128 + cb * 16 + ly) * 2);
                    mma16(oacc[cb * 2],     a, bb[0], bb[1]);
                    mma16(oacc[cb * 2 + 1], a, bb[2], bb[3]);
                }
            }
        }

        // ---- deterministic L reduction ----
#pragma unroll
        for (int h = 0; h < 2; h++) {
            float v = Lacc[h];
            v += __shfl_xor_sync(0xffffffffu, v, 1);
            v += __shfl_xor_sync(0xffffffffu, v, 2);
            if (c2 == 0) Lpart[mg * 64 + qs * 16 + h * 8 + r0] = v;
        }
        __syncthreads();
        if (t < 64)
            Linv[t] = 1.f / (Lpart[t] + Lpart[64 + t] + Lpart[128 + t] + Lpart[192 + t]);
        __syncthreads();

        // ---- epilogue: two 256-channel passes through Ostage (overlays Vs) ----
#pragma unroll
        for (int p = 0; p < 2; p++) {
            if ((mg >> 1) == p) {
                float li0 = Linv[qs * 16 + r0];
                float li1 = Linv[qs * 16 + 8 + r0];
#pragma unroll
                for (int nf = 0; nf < 16; nf++) {
                    int c  = (mg & 1) * 128 + nf * 8 + 2 * c2;
                    int q0 = qs * 16 + r0;
                    Ostage[(c    ) * 68 + q0    ] = oacc[nf][0] * li0;
                    Ostage[(c + 1) * 68 + q0    ] = oacc[nf][1] * li0;
                    Ostage[(c    ) * 68 + q0 + 8] = oacc[nf][2] * li1;
                    Ostage[(c + 1) * 68 + q0 + 8] = oacc[nf][3] * li1;
                }
            }
            __syncthreads();
#pragma unroll
            for (int j = 0; j < 8; j++) {
                int idx = j * 512 + t;
                int c = idx >> 4, q4 = idx & 15;
                float4 o = *(float4*)&Ostage[c * 68 + q4 * 4];
                size_t gidx = ((size_t)(b * NC + p * 256 + c)) * NN + n0 + q4 * 4;
                float4 xv = *(const float4*)(x + gidx);
                float4 rr;
                rr.x = gv2 * o.x + xv.x;
                rr.y = gv2 * o.y + xv.y;
                rr.z = gv2 * o.z + xv.z;
                rr.w = gv2 * o.w + xv.w;
                *(float4*)(out + gidx) = rr;
            }
            __syncthreads();
        }
    }
}

// =========================================================================
extern "C" void kernel_launch(void* const* d_in, const int* in_sizes, int n_in,
                              void* d_out, int out_size)
{
    (void)in_sizes; (void)n_in; (void)out_size;
    const float* x     = (const float*)d_in[0];
    const float* wq    = (const float*)d_in[1];
    const float* bq    = (const float*)d_in[2];
    const float* wk    = (const float*)d_in[3];
    const float* bk    = (const float*)d_in[4];
    const float* wv    = (const float*)d_in[5];
    const float* bv    = (const float*)d_in[6];
    const float* gamma = (const float*)d_in[7];
    float* out = (float*)d_out;

    cudaFuncSetAttribute(pam_proj, cudaFuncAttributeMaxDynamicSharedMemorySize, SMEM_PJ);
    cudaFuncSetAttribute(pam_attn, cudaFuncAttributeMaxDynamicSharedMemorySize, SMEM_AT);

    pam_roundw<<<320, 256>>>(wq, wk, wv);
    pam_proj<<<dim3(NN / 128, 640 / 128, NB), 256, SMEM_PJ>>>(x, bq, bk, bv);
    pam_attn<<<dim3(32, 1, NB), 512, SMEM_AT>>>(x, gamma, out);
}